// round 16
// baseline (speedup 1.0000x reference)
#include <cuda_runtime.h>

#define DD 4096
#define SMSZ 4224   // 4096 + 4096/32 pad floats per row plane

__device__ float g_dev[DD];

__global__ void compute_g_kernel(const float* __restrict__ eps,
                                 const float* __restrict__ g_mu,
                                 const float* __restrict__ g_rho) {
    int i = blockIdx.x * blockDim.x + threadIdx.x;
    if (i < DD) {
        float r = g_rho[i];
        g_dev[i] = g_mu[i] + log1pf(expf(r)) * eps[i];
    }
}

// Scalar radix-16 FWHT over the register index (4 butterfly stages).
__device__ __forceinline__ void fwht16(float v[16]) {
#pragma unroll
    for (int s = 0; s < 4; s++) {
        const int h = 1 << s;
#pragma unroll
        for (int q = 0; q < 16; q += 2*h) {
#pragma unroll
            for (int j = 0; j < h; j++) {
                float a = v[q+j], b = v[q+j+h];
                v[q+j]   = a + b;
                v[q+j+h] = a - b;
            }
        }
    }
}

// y_row = s1 * FWHT( g * FWHT( s2 * x_row ) ),  FWHT_4096 = F_A . F_B . F_C
// (layouts identical to the 41.5us trunk):
//   Phase A: regs = bits {0..3},  lanes = bits {4..8},  warps = bits {9..11}
//   Phase B: regs = bits {4..7},  lanes = bits {0,1,2,8,9}, warps = {3,10,11}
//   Phase C: regs = bits {8..11}, lanes = bits {0..4},  warps = bits {5..7}
// Additive carry-free pad swizzle phys(i) = i + (i>>5); every LDS/STS is
// base register + compile-time immediate, conflict-free (proven at 41.5us).
// NEW vs trunk: TWO rows per CTA as independent scalar chains (v0/v1, two
// smem planes). Barriers amortized 2x, ILP 2x inside every LDS-latency
// window, s1/s2/g loads shared across the pair. Per-row instruction stream
// otherwise identical to the trunk.
__global__ void __launch_bounds__(256, 4)
whvi_kernel(const float* __restrict__ x,
            const float* __restrict__ s1,
            const float* __restrict__ s2,
            float* __restrict__ out) {
    __shared__ float sm[2 * SMSZ];

    const int t = threadIdx.x;
    const int l = t & 31;
    const int w = t >> 5;

    const int baseA = 16*l + 512*w;
    const int baseB = (l & 7) + 8*(w & 1) + 256*(l >> 3) + 1024*(w >> 1);
    const int baseC = l + 32*w;
    const int pA = baseA + (baseA >> 5);
    const int pB = baseB + (baseB >> 5);
    const int pC = baseC + (baseC >> 5);

    const unsigned row0 = 2u * blockIdx.x;
    const float* xr0 = x + row0 * DD + baseA;
    const float* xr1 = xr0 + DD;

    float v0[16], v1[16];

    // ---- P1: coalesced load both rows, *s2 (shared), F_A ----
#pragma unroll
    for (int q = 0; q < 4; q++) {
        float4 s  = *reinterpret_cast<const float4*>(s2 + baseA + 4*q);
        float4 a0 = *reinterpret_cast<const float4*>(xr0 + 4*q);
        float4 a1 = *reinterpret_cast<const float4*>(xr1 + 4*q);
        v0[4*q+0] = a0.x * s.x;  v1[4*q+0] = a1.x * s.x;
        v0[4*q+1] = a0.y * s.y;  v1[4*q+1] = a1.y * s.y;
        v0[4*q+2] = a0.z * s.z;  v1[4*q+2] = a1.z * s.z;
        v0[4*q+3] = a0.w * s.w;  v1[4*q+3] = a1.w * s.w;
    }
    fwht16(v0);
    fwht16(v1);
#pragma unroll
    for (int r = 0; r < 16; r++) {
        sm[pA + r]        = v0[r];
        sm[pA + r + SMSZ] = v1[r];
    }
    __syncthreads();

    // ---- P2: F_B ----  elem offset 16r -> phys offset 16r + (r>>1)
#pragma unroll
    for (int r = 0; r < 16; r++) {
        v0[r] = sm[pB + 16*r + (r >> 1)];
        v1[r] = sm[pB + 16*r + (r >> 1) + SMSZ];
    }
    fwht16(v0);
    fwht16(v1);
#pragma unroll
    for (int r = 0; r < 16; r++) {
        sm[pB + 16*r + (r >> 1)]        = v0[r];
        sm[pB + 16*r + (r >> 1) + SMSZ] = v1[r];
    }
    __syncthreads();

    // ---- P3: F_C, *g (shared load), F_C ----  elem 256r -> phys 264r
#pragma unroll
    for (int r = 0; r < 16; r++) {
        v0[r] = sm[pC + 264*r];
        v1[r] = sm[pC + 264*r + SMSZ];
    }
    fwht16(v0);
    fwht16(v1);
#pragma unroll
    for (int r = 0; r < 16; r++) {
        const float gv = __ldg(&g_dev[baseC + 256*r]);
        v0[r] *= gv;
        v1[r] *= gv;
    }
    fwht16(v0);
    fwht16(v1);
#pragma unroll
    for (int r = 0; r < 16; r++) {
        sm[pC + 264*r]        = v0[r];
        sm[pC + 264*r + SMSZ] = v1[r];
    }
    __syncthreads();

    // ---- P4: F_B ----
#pragma unroll
    for (int r = 0; r < 16; r++) {
        v0[r] = sm[pB + 16*r + (r >> 1)];
        v1[r] = sm[pB + 16*r + (r >> 1) + SMSZ];
    }
    fwht16(v0);
    fwht16(v1);
#pragma unroll
    for (int r = 0; r < 16; r++) {
        sm[pB + 16*r + (r >> 1)]        = v0[r];
        sm[pB + 16*r + (r >> 1) + SMSZ] = v1[r];
    }
    __syncthreads();

    // ---- P5: F_A, *s1 (shared), coalesced store both rows ----
#pragma unroll
    for (int r = 0; r < 16; r++) {
        v0[r] = sm[pA + r];
        v1[r] = sm[pA + r + SMSZ];
    }
    fwht16(v0);
    fwht16(v1);

    float* o0 = out + row0 * DD + baseA;
    float* o1 = o0 + DD;
#pragma unroll
    for (int q = 0; q < 4; q++) {
        float4 s = *reinterpret_cast<const float4*>(s1 + baseA + 4*q);
        float4 a, b;
        a.x = v0[4*q+0] * s.x;  b.x = v1[4*q+0] * s.x;
        a.y = v0[4*q+1] * s.y;  b.y = v1[4*q+1] * s.y;
        a.z = v0[4*q+2] * s.z;  b.z = v1[4*q+2] * s.z;
        a.w = v0[4*q+3] * s.w;  b.w = v1[4*q+3] * s.w;
        *reinterpret_cast<float4*>(o0 + 4*q) = a;
        *reinterpret_cast<float4*>(o1 + 4*q) = b;
    }
}

extern "C" void kernel_launch(void* const* d_in, const int* in_sizes, int n_in,
                              void* d_out, int out_size) {
    const float* x     = (const float*)d_in[0];
    const float* eps   = (const float*)d_in[1];
    const float* s1    = (const float*)d_in[2];
    const float* s2    = (const float*)d_in[3];
    const float* g_mu  = (const float*)d_in[4];
    const float* g_rho = (const float*)d_in[5];
    float* out = (float*)d_out;

    int B = in_sizes[0] / DD;   // 2048

    compute_g_kernel<<<(DD + 255) / 256, 256>>>(eps, g_mu, g_rho);
    whvi_kernel<<<B / 2, 256>>>(x, s1, s2, out);
}